// round 1
// baseline (speedup 1.0000x reference)
#include <cuda_runtime.h>

typedef unsigned long long ull;

#define HH 192
#define BB 16
#define TW 32
#define TH 16
#define NPIX (BB*2*HH*HH)

// ---------- packed f32x2 helpers (sm_103a) ----------
__device__ __forceinline__ ull pk2(float x, float y){ ull r; asm("mov.b64 %0,{%1,%2};":"=l"(r):"f"(x),"f"(y)); return r; }
__device__ __forceinline__ ull dup2(float x){ return pk2(x,x); }
__device__ __forceinline__ void unpk2(ull v, float&x, float&y){ asm("mov.b64 {%0,%1},%2;":"=f"(x),"=f"(y):"l"(v)); }
__device__ __forceinline__ ull ffma2(ull a, ull b, ull c){ ull d; asm("fma.rn.f32x2 %0,%1,%2,%3;":"=l"(d):"l"(a),"l"(b),"l"(c)); return d; }
__device__ __forceinline__ ull fmul2(ull a, ull b){ ull d; asm("mul.rn.f32x2 %0,%1,%2;":"=l"(d):"l"(a),"l"(b)); return d; }
__device__ __forceinline__ ull fadd2(ull a, ull b){ ull d; asm("add.rn.f32x2 %0,%1,%2;":"=l"(d):"l"(a),"l"(b)); return d; }

// ---------- packed constants ----------
// k[]   : 8 stencils (fd00,fd01,fd10,fd02,fd11,fd20, -flipW(fd01), -flipH(fd10)),
//         scaled by dx^-ord, value duplicated into both lanes.
// w0/b0/w1/b1/wf/bf : poly weights, lanes = (poly k=0, poly k=1).
// gw0/gw1/gwf : gradient weight packs for input offsets 1,2:
//         lane0 = weight[k=0][.. index off], lane1 = weight[k=1][.. index 6+off]
struct ConstBlob {
  ull k[200];
  ull w0[24];    // [u*12+i]
  ull b0[2];
  ull w1[26];    // [u*13+i]
  ull b1[2];
  ull wf[14];
  ull bf;
  ull gw0[2][2]; // [off-1][u]
  ull gw1[2][2];
  ull gwf[2];
};

__constant__ ConstBlob cb;
__device__ ConstBlob g_stage;
__device__ float g_uh[NPIX];
__device__ float g_ua[NPIX];
__device__ float g_ub[NPIX];

__global__ void prep_kernel(const float* __restrict__ kern,
                            const float* __restrict__ w0, const float* __restrict__ b0,
                            const float* __restrict__ w1, const float* __restrict__ b1,
                            const float* __restrict__ wf, const float* __restrict__ bf)
{
  int t = threadIdx.x;
  const double dDX = 0.0327249;
  const float s1 = (float)(1.0/dDX);
  const float s2 = (float)(1.0/(dDX*dDX));
  const float sc[6] = {1.f, s1, s1, s2, s2, s2};
  if (t < 200) {
    int d = t/25, r = (t%25)/5, c = t%5;
    float v;
    if (d < 6)       v =  kern[d*25 + r*5 + c] * sc[d];
    else if (d == 6) v = -kern[25 + r*5 + (4-c)] * sc[1];   // -flip along width of fd01
    else             v = -kern[50 + (4-r)*5 + c] * sc[2];   // -flip along height of fd10
    g_stage.k[t] = dup2(v);
  }
  if (t == 0) {
    for (int u = 0; u < 2; u++) {
      for (int i = 0; i < 12; i++) g_stage.w0[u*12+i] = pk2(w0[u*12+i], w0[24+u*12+i]);
      g_stage.b0[u] = pk2(b0[u], b0[2+u]);
      for (int i = 0; i < 13; i++) g_stage.w1[u*13+i] = pk2(w1[u*13+i], w1[26+u*13+i]);
      g_stage.b1[u] = pk2(b1[u], b1[2+u]);
    }
    for (int i = 0; i < 14; i++) g_stage.wf[i] = pk2(wf[i], wf[14+i]);
    g_stage.bf = pk2(bf[0], bf[1]);
    for (int o = 0; o < 2; o++) {
      for (int u = 0; u < 2; u++) {
        g_stage.gw0[o][u] = pk2(w0[u*12 + 1 + o], w0[24 + u*12 + 7 + o]);
        g_stage.gw1[o][u] = pk2(w1[u*13 + 1 + o], w1[26 + u*13 + 7 + o]);
      }
      g_stage.gwf[o] = pk2(wf[1 + o], wf[14 + 7 + o]);
    }
  }
}

// out = ubase + coef * rhs(ueval)
__global__ __launch_bounds__(512)
void rhs_step(const float* __restrict__ ue, const float* __restrict__ ub,
              float coef, float* __restrict__ out)
{
  __shared__ ull tile[TH+4][TW+4];   // (c0,c1) packed per pixel, +2 halo each side

  const int tx = threadIdx.x, ty = threadIdx.y;
  const int tid = ty*TW + tx;
  const int w0_ = blockIdx.x*TW, h0 = blockIdx.y*TH, b = blockIdx.z;

  const float* u0 = ue + (size_t)b*2*HH*HH;
  const float* u1 = u0 + HH*HH;

  for (int e = tid; e < (TH+4)*(TW+4); e += TW*TH) {
    int r = e/(TW+4), c = e%(TW+4);
    int h = h0 + r - 2; if (h < 0) h += HH; if (h >= HH) h -= HH;
    int w = w0_ + c - 2; if (w < 0) w += HH; if (w >= HH) w -= HH;
    tile[r][c] = pk2(u0[h*HH+w], u1[h*HH+w]);
  }
  __syncthreads();

  // ---- 8 correlations for both channels at once (packed) ----
  ull acc[8];
  #pragma unroll
  for (int d = 0; d < 8; d++) acc[d] = 0ull;
  #pragma unroll
  for (int i = 0; i < 5; i++) {
    #pragma unroll
    for (int j = 0; j < 5; j++) {
      ull v = tile[ty+i][tx+j];
      #pragma unroll
      for (int d = 0; d < 8; d++) acc[d] = ffma2(cb.k[d*25 + i*5 + j], v, acc[d]);
    }
  }

  float X[12];
  #pragma unroll
  for (int d = 0; d < 6; d++) unpk2(acc[d], X[d], X[6+d]);
  float f01x, f01y, f10x, f10y;
  unpk2(acc[6], f01x, f01y);
  unpk2(acc[7], f10x, f10y);

  // ---- poly linear parts at base (lanes = poly k0,k1) ----
  ull p2 = cb.b0[0], q2 = cb.b0[1], rl = cb.b1[0], sl = cb.b1[1], ol = cb.bf;
  #pragma unroll
  for (int i = 0; i < 12; i++) {
    ull xd = dup2(X[i]);
    p2 = ffma2(cb.w0[i],    xd, p2);
    q2 = ffma2(cb.w0[12+i], xd, q2);
    rl = ffma2(cb.w1[i],    xd, rl);
    sl = ffma2(cb.w1[13+i], xd, sl);
    ol = ffma2(cb.wf[i],    xd, ol);
  }
  ull m1 = fmul2(p2, q2);
  ull r2 = ffma2(cb.w1[12], m1, rl);
  ull s2 = ffma2(cb.w1[25], m1, sl);

  // ---- analytic gradient at base: d(poly_k)/dX[k*6+off], off=1,2 ----
  ull g2[2];
  #pragma unroll
  for (int o = 0; o < 2; o++) {
    ull dm1 = fadd2(fmul2(q2, cb.gw0[o][0]), fmul2(p2, cb.gw0[o][1]));
    ull dr  = ffma2(cb.w1[12], dm1, cb.gw1[o][0]);
    ull ds  = ffma2(cb.w1[25], dm1, cb.gw1[o][1]);
    ull dm2 = fadd2(fmul2(s2, dr), fmul2(r2, ds));
    ull g   = ffma2(cb.wf[12], dm1, cb.gwf[o]);
    g2[o]   = ffma2(cb.wf[13], dm2, g);
  }
  float g01a, g01b, g10a, g10b;
  unpk2(g2[0], g01a, g01b);
  unpk2(g2[1], g10a, g10b);

  // upwind deltas (0 if keep base, else flipped - base)
  float d1 = (g01a > 0.f) ? 0.f : (f01x - X[1]);
  float d7 = (g01b > 0.f) ? 0.f : (f01y - X[7]);
  float d2 = (g10a > 0.f) ? 0.f : (f10x - X[2]);
  float d8 = (g10b > 0.f) ? 0.f : (f10y - X[8]);
  ull D1 = dup2(d1), D2 = dup2(d2), D7 = dup2(d7), D8 = dup2(d8);

  // ---- delta-update linear parts to Xsel, finish poly ----
  p2 = ffma2(cb.w0[1], D1, ffma2(cb.w0[2], D2, ffma2(cb.w0[7], D7, ffma2(cb.w0[8], D8, p2))));
  q2 = ffma2(cb.w0[13], D1, ffma2(cb.w0[14], D2, ffma2(cb.w0[19], D7, ffma2(cb.w0[20], D8, q2))));
  rl = ffma2(cb.w1[1], D1, ffma2(cb.w1[2], D2, ffma2(cb.w1[7], D7, ffma2(cb.w1[8], D8, rl))));
  sl = ffma2(cb.w1[14], D1, ffma2(cb.w1[15], D2, ffma2(cb.w1[20], D7, ffma2(cb.w1[21], D8, sl))));
  ol = ffma2(cb.wf[1], D1, ffma2(cb.wf[2], D2, ffma2(cb.wf[7], D7, ffma2(cb.wf[8], D8, ol))));

  m1 = fmul2(p2, q2);
  r2 = ffma2(cb.w1[12], m1, rl);
  s2 = ffma2(cb.w1[25], m1, sl);
  ull m2 = fmul2(r2, s2);
  ull o2 = ffma2(cb.wf[12], m1, ol);
  o2 = ffma2(cb.wf[13], m2, o2);

  float ua0, ua1;
  unpk2(o2, ua0, ua1);

  const int h = h0 + ty, w = w0_ + tx;
  const size_t i0 = ((size_t)(b*2))*HH*HH + (size_t)h*HH + w;
  out[i0]         = ub[i0]         + coef*ua0;
  out[i0 + HH*HH] = ub[i0 + HH*HH] + coef*ua1;
}

extern "C" void kernel_launch(void* const* d_in, const int* in_sizes, int n_in,
                              void* d_out, int out_size)
{
  (void)in_sizes; (void)n_in; (void)out_size;
  const float* init = (const float*)d_in[0];
  const float* kern = (const float*)d_in[1];
  const float* w0   = (const float*)d_in[2];
  const float* b0   = (const float*)d_in[3];
  const float* w1   = (const float*)d_in[4];
  const float* b1   = (const float*)d_in[5];
  const float* wf   = (const float*)d_in[6];
  const float* bf   = (const float*)d_in[7];
  float* out = (float*)d_out;

  void *puh, *pua, *pub, *pstage;
  cudaGetSymbolAddress(&puh, g_uh);
  cudaGetSymbolAddress(&pua, g_ua);
  cudaGetSymbolAddress(&pub, g_ub);
  cudaGetSymbolAddress(&pstage, g_stage);

  prep_kernel<<<1, 256>>>(kern, w0, b0, w1, b1, wf, bf);
  cudaMemcpyToSymbolAsync(cb, pstage, sizeof(ConstBlob), 0, cudaMemcpyDeviceToDevice, 0);

  dim3 grid(HH/TW, HH/TH, BB);
  dim3 block(TW, TH);

  const float DT = 0.2f;
  const float* ucur = init;
  for (int s = 0; s < 5; s++) {
    float* un = (s == 4) ? out : ((s & 1) ? (float*)pub : (float*)pua);
    rhs_step<<<grid, block>>>(ucur, ucur, DT*0.5f, (float*)puh);
    rhs_step<<<grid, block>>>((float*)puh, ucur, DT, un);
    ucur = un;
  }
}